// round 16
// baseline (speedup 1.0000x reference)
#include <cuda_runtime.h>
#include <cuda_fp16.h>

#define NN 50000
#define NE 600000
#define HID 128

#define SCAN_BS 256
#define SCAN_VT 8
#define SCAN_ELEMS (SCAN_BS * SCAN_VT)                    // 2048
#define SCAN_NBLK ((NN + SCAN_ELEMS - 1) / SCAN_ELEMS)    // 25 (per side)

#define ASTRIDE 136

typedef unsigned long long u64;
typedef unsigned int u32;

// ---- scratch (per-side CSR) ----
__device__ int    g_cnt_n[NN];
__device__ int    g_cnt_e[NN];
__device__ int    g_offs_n[NN + 1];
__device__ int    g_offs_e[NN + 1];
__device__ u32    g_look_n[SCAN_NBLK];
__device__ u32    g_look_e[SCAN_NBLK];
__device__ int    g_csr_n[NE];
__device__ int    g_csr_e[NE];
__device__ float  g_dinv[NN];
__device__ float  g_binv[NN];
__device__ __half g_xh[NN * HID];
__device__ __half g_w1h[HID * HID];
__device__ __half g_w2h[HID * HID];
__device__ __half g_xw[NN * HID];
__device__ __half g_m[NN * HID];
__device__ __half g_h[NN * HID];
__device__ int    g_is_i32;

// ---- streams + events ----
struct SideStream {
    cudaStream_t s1, s2;
    cudaEvent_t evStart, evDetect, evScanE, evScanN, evGemm, evFillE2, evFillN;
    SideStream() {
        cudaStreamCreateWithFlags(&s1, cudaStreamNonBlocking);
        cudaStreamCreateWithFlags(&s2, cudaStreamNonBlocking);
        cudaEventCreateWithFlags(&evStart, cudaEventDisableTiming);
        cudaEventCreateWithFlags(&evDetect, cudaEventDisableTiming);
        cudaEventCreateWithFlags(&evScanE, cudaEventDisableTiming);
        cudaEventCreateWithFlags(&evScanN, cudaEventDisableTiming);
        cudaEventCreateWithFlags(&evGemm, cudaEventDisableTiming);
        cudaEventCreateWithFlags(&evFillE2, cudaEventDisableTiming);
        cudaEventCreateWithFlags(&evFillN, cudaEventDisableTiming);
    }
};
static SideStream g_ss;

// ---- PTX helpers ----
__device__ __forceinline__ u32 sptr(const void* p) {
    return (u32)__cvta_generic_to_shared(p);
}
__device__ __forceinline__ void ldsm4(u32& r0, u32& r1, u32& r2, u32& r3, u32 a) {
    asm volatile("ldmatrix.sync.aligned.m8n8.x4.shared.b16 {%0,%1,%2,%3},[%4];"
                 : "=r"(r0), "=r"(r1), "=r"(r2), "=r"(r3) : "r"(a));
}
__device__ __forceinline__ void ldsm4t(u32& r0, u32& r1, u32& r2, u32& r3, u32 a) {
    asm volatile("ldmatrix.sync.aligned.m8n8.x4.trans.shared.b16 {%0,%1,%2,%3},[%4];"
                 : "=r"(r0), "=r"(r1), "=r"(r2), "=r"(r3) : "r"(a));
}
__device__ __forceinline__ void mma16816(float* d, const u32* a, const u32* b) {
    asm volatile("mma.sync.aligned.m16n8k16.row.col.f32.f16.f16.f32 "
                 "{%0,%1,%2,%3},{%4,%5,%6,%7},{%8,%9},{%0,%1,%2,%3};"
                 : "+f"(d[0]), "+f"(d[1]), "+f"(d[2]), "+f"(d[3])
                 : "r"(a[0]), "r"(a[1]), "r"(a[2]), "r"(a[3]), "r"(b[0]), "r"(b[1]));
}

// ---- zero (edge side) + lookback flags + dtype detect in block 0 ----
__global__ void k_zero_e_detect(const long long* __restrict__ hei64) {
    int i = blockIdx.x * blockDim.x + threadIdx.x;
    if (i < NN) g_cnt_e[i] = 0;
    if (i < SCAN_NBLK) g_look_e[i] = 0;
    if (blockIdx.x == 0) {
        int tid = threadIdx.x;
        int bad = 0;
#pragma unroll
        for (int t = 0; t < 16; t++) {
            long long v = hei64[tid * 16 + t];
            if (v < 0 || v >= NN) bad = 1;
        }
        __shared__ int sbad[8];
        unsigned wb = __ballot_sync(0xffffffffu, bad);
        if ((tid & 31) == 0) sbad[tid >> 5] = (wb != 0);
        __syncthreads();
        if (tid == 0) {
            int any = 0;
            for (int w = 0; w < 8; w++) any |= sbad[w];
            g_is_i32 = any;
        }
    }
}

__global__ void k_zero_n() {
    int i = blockIdx.x * blockDim.x + threadIdx.x;
    if (i < NN) g_cnt_n[i] = 0;
    if (i < SCAN_NBLK) g_look_n[i] = 0;
}

__device__ __forceinline__ int clampi(int v) {
    return (v < 0 || v >= NN) ? 0 : v;
}

// ---- per-side degree counts (2 entries / thread) ----
__global__ void k_deg_side(const void* __restrict__ hei, int row, int* __restrict__ cnt) {
    int t = blockIdx.x * blockDim.x + threadIdx.x;
    int i0 = t * 2;
    if (i0 >= NE) return;
    bool i32 = (g_is_i32 != 0);
    long long base = (long long)row * NE;
#pragma unroll
    for (int k = 0; k < 2; k++) {
        int i = i0 + k;
        int v;
        if (i32) v = ((const int*)hei)[base + i];
        else     v = (int)((const long long*)hei)[base + i];
        atomicAdd(&cnt[clampi(v)], 1);
    }
}

// ---- single-pass scan with decoupled lookback + inverse degrees ----
__global__ __launch_bounds__(SCAN_BS) void k_scan_s(const int* __restrict__ cnt,
                                                    int* __restrict__ offs,
                                                    u32* __restrict__ look,
                                                    float* __restrict__ inv) {
    __shared__ int s[SCAN_BS];
    __shared__ int sprefix;
    int blk = blockIdx.x, tid = threadIdx.x;
    int base = blk * SCAN_ELEMS + tid * SCAN_VT;
    int v[SCAN_VT];
    int sum = 0;
#pragma unroll
    for (int t = 0; t < SCAN_VT; t++) {
        v[t] = (base + t < NN) ? cnt[base + t] : 0;
        sum += v[t];
    }
    s[tid] = sum;
    __syncthreads();
    for (int off = 1; off < SCAN_BS; off <<= 1) {
        int t = (tid >= off) ? s[tid - off] : 0;
        __syncthreads();
        s[tid] += t;
        __syncthreads();
    }
    int btotal = s[SCAN_BS - 1];

    if (tid == 0) {
        int prefix = 0;
        if (blk == 0) {
            atomicExch(&look[0], (u32)btotal | (2u << 24));
        } else {
            atomicExch(&look[blk], (u32)btotal | (1u << 24));
            int idx = blk - 1;
            while (true) {
                u32 w = atomicAdd(&look[idx], 0u);
                u32 st = w >> 24;
                if (st == 0) continue;
                prefix += (int)(w & 0xFFFFFFu);
                if (st == 2u) break;
                idx--;
            }
            atomicExch(&look[blk], (u32)(prefix + btotal) | (2u << 24));
        }
        sprefix = prefix;
    }
    __syncthreads();
    int run = sprefix + s[tid] - sum;
#pragma unroll
    for (int t = 0; t < SCAN_VT; t++) {
        int i = base + t;
        if (i < NN) {
            offs[i] = run;
            int c = v[t];
            inv[i] = c > 0 ? 1.0f / (float)c : 0.0f;
            run += c;
        }
    }
    if (blk == 0 && tid == 0) offs[NN] = NE;
}

__device__ __forceinline__ void decode(const void* hei, bool i32, int i, int& n, int& e) {
    if (i32) {
        n = ((const int*)hei)[i];
        e = ((const int*)hei)[NE + i];
    } else {
        n = (int)((const long long*)hei)[i];
        e = (int)((const long long*)hei)[NE + i];
    }
    n = clampi(n);
    e = clampi(e);
}

// ---- CSR fill per side, entry-range versions (1 entry / thread) ----
__global__ void k_fill_e(const void* __restrict__ hei, int lo, int hi) {
    int i = lo + blockIdx.x * blockDim.x + threadIdx.x;
    if (i >= hi) return;
    bool i32 = (g_is_i32 != 0);
    int n, e;
    decode(hei, i32, i, n, e);
    int pe = g_offs_e[e] + atomicSub(&g_cnt_e[e], 1) - 1;
    g_csr_e[pe] = n;
}

__global__ void k_fill_n(const void* __restrict__ hei, int lo, int hi) {
    int i = lo + blockIdx.x * blockDim.x + threadIdx.x;
    if (i >= hi) return;
    bool i32 = (g_is_i32 != 0);
    int n, e;
    decode(hei, i32, i, n, e);
    int pn = g_offs_n[n] + atomicSub(&g_cnt_n[n], 1) - 1;
    g_csr_n[pn] = e;
}

// ---- fp32 -> fp16 convert ----
__global__ void k_f2h(const float* __restrict__ src, __half* __restrict__ dst, int n4) {
    int i = blockIdx.x * blockDim.x + threadIdx.x;
    if (i < n4) {
        float4 v = ((const float4*)src)[i];
        __half2 h0 = __floats2half2_rn(v.x, v.y);
        __half2 h1 = __floats2half2_rn(v.z, v.w);
        uint2 o;
        o.x = *(u32*)&h0;
        o.y = *(u32*)&h1;
        ((uint2*)dst)[i] = o;
    }
}

// ---- tensor-core GEMM ----
__global__ __launch_bounds__(256) void k_gemm_mma(const __half* __restrict__ A,
                                                  const __half* __restrict__ Wh,
                                                  __half* __restrict__ C, int M) {
    extern __shared__ __half smem[];
    __half* sA = smem;
    __half* sB = smem + 128 * ASTRIDE;
    int tid = threadIdx.x;
    int rb = blockIdx.x * 128;

#pragma unroll
    for (int it = 0; it < 8; it++) {
        int idx = (it * 256 + tid) * 8;
        int r = idx >> 7, c = idx & 127;
        uint4 v = make_uint4(0, 0, 0, 0);
        if (rb + r < M) v = *(const uint4*)(A + (size_t)(rb + r) * HID + c);
        *(uint4*)(sA + r * ASTRIDE + c) = v;
    }
#pragma unroll
    for (int it = 0; it < 8; it++) {
        int idx = (it * 256 + tid) * 8;
        int r = idx >> 7, c = idx & 127;
        *(uint4*)(sB + r * ASTRIDE + c) = *(const uint4*)(Wh + r * HID + c);
    }
    __syncthreads();

    int w = tid >> 5, lane = tid & 31;
    int wm = (w & 3) * 32;
    int wn = (w >> 2) * 64;
    int lrow = (lane & 7) + ((lane >> 3) & 1) * 8;
    int lcol8 = (lane >> 4) * 8;

    float acc[2][8][4];
#pragma unroll
    for (int mi = 0; mi < 2; mi++)
#pragma unroll
        for (int nj = 0; nj < 8; nj++)
#pragma unroll
            for (int q = 0; q < 4; q++) acc[mi][nj][q] = 0.f;

#pragma unroll
    for (int ks = 0; ks < 8; ks++) {
        int k0 = ks * 16;
        u32 a[2][4];
#pragma unroll
        for (int mi = 0; mi < 2; mi++) {
            u32 ad = sptr(sA + (wm + mi * 16 + lrow) * ASTRIDE + k0 + lcol8);
            ldsm4(a[mi][0], a[mi][1], a[mi][2], a[mi][3], ad);
        }
        u32 b[8][2];
#pragma unroll
        for (int nj = 0; nj < 4; nj++) {
            u32 ad = sptr(sB + (k0 + lrow) * ASTRIDE + wn + nj * 16 + lcol8);
            u32 r0, r1, r2, r3;
            ldsm4t(r0, r1, r2, r3, ad);
            b[nj * 2][0] = r0; b[nj * 2][1] = r1;
            b[nj * 2 + 1][0] = r2; b[nj * 2 + 1][1] = r3;
        }
#pragma unroll
        for (int mi = 0; mi < 2; mi++)
#pragma unroll
            for (int nj = 0; nj < 8; nj++)
                mma16816(acc[mi][nj], a[mi], b[nj]);
    }

    int g = lane >> 2, t4 = lane & 3;
#pragma unroll
    for (int mi = 0; mi < 2; mi++) {
        int r0 = rb + wm + mi * 16 + g;
        int r1 = r0 + 8;
#pragma unroll
        for (int nj = 0; nj < 8; nj++) {
            int col = wn + nj * 8 + t4 * 2;
            if (r0 < M) {
                __half2 h = __floats2half2_rn(acc[mi][nj][0], acc[mi][nj][1]);
                *(__half2*)(C + (size_t)r0 * HID + col) = h;
            }
            if (r1 < M) {
                __half2 h = __floats2half2_rn(acc[mi][nj][2], acc[mi][nj][3]);
                *(__half2*)(C + (size_t)r1 * HID + col) = h;
            }
        }
    }
}

// ---- accumulate helper ----
__device__ __forceinline__ void acc_row(float4& acc, uint2 u) {
    float2 a0 = __half22float2(*(const __half2*)&u.x);
    float2 a1 = __half22float2(*(const __half2*)&u.y);
    acc.x += a0.x; acc.y += a0.y; acc.z += a1.x; acc.w += a1.y;
}

// ---- edge gather: m[e] = binv[e] * sum xw[n], 4-way unrolled ----
__global__ __launch_bounds__(256) void k_gather_e(const __half* __restrict__ src,
                                                  __half* __restrict__ dst) {
    int g = blockIdx.x * blockDim.x + threadIdx.x;
    int e = g >> 5;
    int lane = g & 31;
    if (e >= NN) return;
    int beg = g_offs_e[e];
    int end = g_offs_e[e + 1];
    float4 acc = make_float4(0.f, 0.f, 0.f, 0.f);
    const uint2* s2 = (const uint2*)src;
    int j = beg;
    for (; j + 3 < end; j += 4) {
        int i0 = g_csr_e[j], i1 = g_csr_e[j + 1], i2 = g_csr_e[j + 2], i3 = g_csr_e[j + 3];
        uint2 u0 = s2[(size_t)i0 * 32 + lane];
        uint2 u1 = s2[(size_t)i1 * 32 + lane];
        uint2 u2 = s2[(size_t)i2 * 32 + lane];
        uint2 u3 = s2[(size_t)i3 * 32 + lane];
        acc_row(acc, u0); acc_row(acc, u1); acc_row(acc, u2); acc_row(acc, u3);
    }
    for (; j < end; j++) {
        uint2 u0 = s2[(size_t)g_csr_e[j] * 32 + lane];
        acc_row(acc, u0);
    }
    float s = g_binv[e];
    __half2 o0 = __floats2half2_rn(acc.x * s, acc.y * s);
    __half2 o1 = __floats2half2_rn(acc.z * s, acc.w * s);
    uint2 ov;
    ov.x = *(const u32*)&o0;
    ov.y = *(const u32*)&o1;
    ((uint2*)dst)[(size_t)e * 32 + lane] = ov;
}

// ---- node gather, 4-way unrolled ----
template <bool RES, typename OUT>
__global__ __launch_bounds__(256) void k_gather_n(const __half* __restrict__ src,
                                                  const float* __restrict__ bias,
                                                  const float* __restrict__ pa,
                                                  const float* __restrict__ xres,
                                                  OUT* __restrict__ dst) {
    int g = blockIdx.x * blockDim.x + threadIdx.x;
    int n = g >> 5;
    int lane = g & 31;
    if (n >= NN) return;
    int beg = g_offs_n[n];
    int end = g_offs_n[n + 1];
    float4 acc = make_float4(0.f, 0.f, 0.f, 0.f);
    const uint2* s2 = (const uint2*)src;
    int j = beg;
    for (; j + 3 < end; j += 4) {
        int i0 = g_csr_n[j], i1 = g_csr_n[j + 1], i2 = g_csr_n[j + 2], i3 = g_csr_n[j + 3];
        uint2 u0 = s2[(size_t)i0 * 32 + lane];
        uint2 u1 = s2[(size_t)i1 * 32 + lane];
        uint2 u2 = s2[(size_t)i2 * 32 + lane];
        uint2 u3 = s2[(size_t)i3 * 32 + lane];
        acc_row(acc, u0); acc_row(acc, u1); acc_row(acc, u2); acc_row(acc, u3);
    }
    for (; j < end; j++) {
        uint2 u0 = s2[(size_t)g_csr_n[j] * 32 + lane];
        acc_row(acc, u0);
    }
    float d = g_dinv[n];
    float a = pa[0];
    float4 b = ((const float4*)bias)[lane];
    acc.x = acc.x * d + b.x;
    acc.y = acc.y * d + b.y;
    acc.z = acc.z * d + b.z;
    acc.w = acc.w * d + b.w;
    if (RES) {
        float4 xv = ((const float4*)xres)[(size_t)n * 32 + lane];
        acc.x += xv.x; acc.y += xv.y; acc.z += xv.z; acc.w += xv.w;
    }
    acc.x = acc.x >= 0.f ? acc.x : a * acc.x;
    acc.y = acc.y >= 0.f ? acc.y : a * acc.y;
    acc.z = acc.z >= 0.f ? acc.z : a * acc.z;
    acc.w = acc.w >= 0.f ? acc.w : a * acc.w;
    if (sizeof(OUT) == 2) {
        __half2 o0 = __floats2half2_rn(acc.x, acc.y);
        __half2 o1 = __floats2half2_rn(acc.z, acc.w);
        uint2 ov;
        ov.x = *(const u32*)&o0;
        ov.y = *(const u32*)&o1;
        ((uint2*)dst)[(size_t)n * 32 + lane] = ov;
    } else {
        ((float4*)dst)[(size_t)n * 32 + lane] = acc;
    }
}

extern "C" void kernel_launch(void* const* d_in, const int* in_sizes, int n_in,
                              void* d_out, int out_size) {
    (void)in_sizes; (void)n_in; (void)out_size;
    const float* x   = (const float*)d_in[0];
    const void*  hei = d_in[1];
    const float* W1  = (const float*)d_in[2];
    const float* b1  = (const float*)d_in[3];
    const float* W2  = (const float*)d_in[4];
    const float* b2  = (const float*)d_in[5];
    const float* pa  = (const float*)d_in[6];
    float* out = (float*)d_out;

    __half *pxh, *pw1h, *pw2h, *pxw, *pm, *ph;
    int *pcn, *pce, *pon, *poe;
    u32 *pln, *ple;
    float *pdi, *pbi;
    cudaGetSymbolAddress((void**)&pxh,  g_xh);
    cudaGetSymbolAddress((void**)&pw1h, g_w1h);
    cudaGetSymbolAddress((void**)&pw2h, g_w2h);
    cudaGetSymbolAddress((void**)&pxw,  g_xw);
    cudaGetSymbolAddress((void**)&pm,   g_m);
    cudaGetSymbolAddress((void**)&ph,   g_h);
    cudaGetSymbolAddress((void**)&pcn,  g_cnt_n);
    cudaGetSymbolAddress((void**)&pce,  g_cnt_e);
    cudaGetSymbolAddress((void**)&pon,  g_offs_n);
    cudaGetSymbolAddress((void**)&poe,  g_offs_e);
    cudaGetSymbolAddress((void**)&pln,  g_look_n);
    cudaGetSymbolAddress((void**)&ple,  g_look_e);
    cudaGetSymbolAddress((void**)&pdi,  g_dinv);
    cudaGetSymbolAddress((void**)&pbi,  g_binv);

    const int GW_BLOCKS = (NN * 32) / 256;
    const int GEMM_SMEM = 2 * 128 * ASTRIDE * 2;
    const int HALF = NE / 2;
    const int FILL_HALF_BLOCKS = (HALF + 255) / 256;
    cudaFuncSetAttribute(k_gemm_mma, cudaFuncAttributeMaxDynamicSharedMemorySize, GEMM_SMEM);

    // fork
    cudaEventRecord(g_ss.evStart, 0);
    cudaStreamWaitEvent(g_ss.s1, g_ss.evStart, 0);
    cudaStreamWaitEvent(g_ss.s2, g_ss.evStart, 0);

    // stream 0: EDGE-side chain; fill_e half 0
    k_zero_e_detect<<<(NN + 255) / 256, 256>>>((const long long*)hei);
    cudaEventRecord(g_ss.evDetect, 0);
    k_deg_side<<<(NE / 2 + 255) / 256, 256>>>(hei, 1, pce);
    k_scan_s<<<SCAN_NBLK, SCAN_BS>>>(pce, poe, ple, pbi);
    cudaEventRecord(g_ss.evScanE, 0);
    k_fill_e<<<FILL_HALF_BLOCKS, 256>>>(hei, 0, HALF);

    // s2: node degree chain; fill_e half 1; then node scan
    k_zero_n<<<(NN + 255) / 256, 256, 0, g_ss.s2>>>();
    cudaStreamWaitEvent(g_ss.s2, g_ss.evDetect, 0);
    k_deg_side<<<(NE / 2 + 255) / 256, 256, 0, g_ss.s2>>>(hei, 0, pcn);
    cudaStreamWaitEvent(g_ss.s2, g_ss.evScanE, 0);
    k_fill_e<<<FILL_HALF_BLOCKS, 256, 0, g_ss.s2>>>(hei, HALF, NE);
    cudaEventRecord(g_ss.evFillE2, g_ss.s2);
    k_scan_s<<<SCAN_NBLK, SCAN_BS, 0, g_ss.s2>>>(pcn, pon, pln, pdi);
    cudaEventRecord(g_ss.evScanN, g_ss.s2);

    // s1: fp16 conversions + GEMM1; then full fill_n (idle slot after GEMM1)
    k_f2h<<<(NN * HID / 4 + 255) / 256, 256, 0, g_ss.s1>>>(x, pxh, NN * HID / 4);
    k_f2h<<<(HID * HID / 4 + 255) / 256, 256, 0, g_ss.s1>>>(W1, pw1h, HID * HID / 4);
    k_f2h<<<(HID * HID / 4 + 255) / 256, 256, 0, g_ss.s1>>>(W2, pw2h, HID * HID / 4);
    k_gemm_mma<<<(NN + 127) / 128, 256, GEMM_SMEM, g_ss.s1>>>(pxh, pw1h, pxw, NN);
    cudaEventRecord(g_ss.evGemm, g_ss.s1);
    cudaStreamWaitEvent(g_ss.s1, g_ss.evScanN, 0);
    k_fill_n<<<(NE + 255) / 256, 256, 0, g_ss.s1>>>(hei, 0, NE);
    cudaEventRecord(g_ss.evFillN, g_ss.s1);

    // layer 1 aggregation on stream 0
    cudaStreamWaitEvent(0, g_ss.evGemm, 0);
    cudaStreamWaitEvent(0, g_ss.evFillE2, 0);
    k_gather_e<<<GW_BLOCKS, 256>>>(pxw, pm);
    cudaStreamWaitEvent(0, g_ss.evFillN, 0);
    k_gather_n<false, __half><<<GW_BLOCKS, 256>>>(pm, b1, pa, nullptr, ph);

    // layer 2
    k_gemm_mma<<<(NN + 127) / 128, 256, GEMM_SMEM>>>(ph, pw2h, pxw, NN);
    k_gather_e<<<GW_BLOCKS, 256>>>(pxw, pm);
    k_gather_n<true, float><<<GW_BLOCKS, 256>>>(pm, b2, pa, x, out);
}

// round 17
// speedup vs baseline: 1.0489x; 1.0489x over previous
#include <cuda_runtime.h>
#include <cuda_fp16.h>

#define NN 50000
#define NE 600000
#define HID 128

#define SCAN_BS 256
#define SCAN_VT 8
#define SCAN_ELEMS (SCAN_BS * SCAN_VT)                    // 2048
#define SCAN_NBLK ((NN + SCAN_ELEMS - 1) / SCAN_ELEMS)    // 25 (per side)

#define ASTRIDE 136

typedef unsigned long long u64;
typedef unsigned int u32;

// ---- scratch (per-side CSR) ----
__device__ int    g_cnt_n[NN];   // after scan: end-cursor (offs + degree)
__device__ int    g_cnt_e[NN];
__device__ int    g_offs_n[NN + 1];
__device__ int    g_offs_e[NN + 1];
__device__ u32    g_look_n[SCAN_NBLK];
__device__ u32    g_look_e[SCAN_NBLK];
__device__ int    g_csr_n[NE];
__device__ int    g_csr_e[NE];
__device__ float  g_dinv[NN];
__device__ float  g_binv[NN];
__device__ __half g_xh[NN * HID];
__device__ __half g_w1h[HID * HID];
__device__ __half g_w2h[HID * HID];
__device__ __half g_xw[NN * HID];
__device__ __half g_m[NN * HID];
__device__ __half g_h[NN * HID];
__device__ int    g_is_i32;

// ---- streams + events ----
struct SideStream {
    cudaStream_t s1, s2;
    cudaEvent_t evStart, evDetect, evGemm, evFillN;
    SideStream() {
        cudaStreamCreateWithFlags(&s1, cudaStreamNonBlocking);
        cudaStreamCreateWithFlags(&s2, cudaStreamNonBlocking);
        cudaEventCreateWithFlags(&evStart, cudaEventDisableTiming);
        cudaEventCreateWithFlags(&evDetect, cudaEventDisableTiming);
        cudaEventCreateWithFlags(&evGemm, cudaEventDisableTiming);
        cudaEventCreateWithFlags(&evFillN, cudaEventDisableTiming);
    }
};
static SideStream g_ss;

// ---- PTX helpers ----
__device__ __forceinline__ u32 sptr(const void* p) {
    return (u32)__cvta_generic_to_shared(p);
}
__device__ __forceinline__ void ldsm4(u32& r0, u32& r1, u32& r2, u32& r3, u32 a) {
    asm volatile("ldmatrix.sync.aligned.m8n8.x4.shared.b16 {%0,%1,%2,%3},[%4];"
                 : "=r"(r0), "=r"(r1), "=r"(r2), "=r"(r3) : "r"(a));
}
__device__ __forceinline__ void ldsm4t(u32& r0, u32& r1, u32& r2, u32& r3, u32 a) {
    asm volatile("ldmatrix.sync.aligned.m8n8.x4.trans.shared.b16 {%0,%1,%2,%3},[%4];"
                 : "=r"(r0), "=r"(r1), "=r"(r2), "=r"(r3) : "r"(a));
}
__device__ __forceinline__ void mma16816(float* d, const u32* a, const u32* b) {
    asm volatile("mma.sync.aligned.m16n8k16.row.col.f32.f16.f16.f32 "
                 "{%0,%1,%2,%3},{%4,%5,%6,%7},{%8,%9},{%0,%1,%2,%3};"
                 : "+f"(d[0]), "+f"(d[1]), "+f"(d[2]), "+f"(d[3])
                 : "r"(a[0]), "r"(a[1]), "r"(a[2]), "r"(a[3]), "r"(b[0]), "r"(b[1]));
}

// ---- zero (edge side) + lookback flags + dtype detect in block 0 ----
__global__ void k_zero_e_detect(const long long* __restrict__ hei64) {
    int i = blockIdx.x * blockDim.x + threadIdx.x;
    if (i < NN) g_cnt_e[i] = 0;
    if (i < SCAN_NBLK) g_look_e[i] = 0;
    if (blockIdx.x == 0) {
        int tid = threadIdx.x;
        int bad = 0;
#pragma unroll
        for (int t = 0; t < 16; t++) {
            long long v = hei64[tid * 16 + t];
            if (v < 0 || v >= NN) bad = 1;
        }
        __shared__ int sbad[8];
        unsigned wb = __ballot_sync(0xffffffffu, bad);
        if ((tid & 31) == 0) sbad[tid >> 5] = (wb != 0);
        __syncthreads();
        if (tid == 0) {
            int any = 0;
            for (int w = 0; w < 8; w++) any |= sbad[w];
            g_is_i32 = any;
        }
    }
}

__global__ void k_zero_n() {
    int i = blockIdx.x * blockDim.x + threadIdx.x;
    if (i < NN) g_cnt_n[i] = 0;
    if (i < SCAN_NBLK) g_look_n[i] = 0;
}

__device__ __forceinline__ int clampi(int v) {
    return (v < 0 || v >= NN) ? 0 : v;
}

// ---- per-side degree counts (2 entries / thread) ----
__global__ void k_deg_side(const void* __restrict__ hei, int row, int* __restrict__ cnt) {
    int t = blockIdx.x * blockDim.x + threadIdx.x;
    int i0 = t * 2;
    if (i0 >= NE) return;
    bool i32 = (g_is_i32 != 0);
    long long base = (long long)row * NE;
#pragma unroll
    for (int k = 0; k < 2; k++) {
        int i = i0 + k;
        int v;
        if (i32) v = ((const int*)hei)[base + i];
        else     v = (int)((const long long*)hei)[base + i];
        atomicAdd(&cnt[clampi(v)], 1);
    }
}

// ---- single-pass scan with decoupled lookback + inverse degrees ----
// Also rewrites cnt[i] = offs[i] + degree (end-cursor) so the fill kernels
// need no separate offs load (shorter atomic dependency chain).
__global__ __launch_bounds__(SCAN_BS) void k_scan_s(int* cnt,
                                                    int* __restrict__ offs,
                                                    u32* __restrict__ look,
                                                    float* __restrict__ inv) {
    __shared__ int s[SCAN_BS];
    __shared__ int sprefix;
    int blk = blockIdx.x, tid = threadIdx.x;
    int base = blk * SCAN_ELEMS + tid * SCAN_VT;
    int v[SCAN_VT];
    int sum = 0;
#pragma unroll
    for (int t = 0; t < SCAN_VT; t++) {
        v[t] = (base + t < NN) ? cnt[base + t] : 0;
        sum += v[t];
    }
    s[tid] = sum;
    __syncthreads();
    for (int off = 1; off < SCAN_BS; off <<= 1) {
        int t = (tid >= off) ? s[tid - off] : 0;
        __syncthreads();
        s[tid] += t;
        __syncthreads();
    }
    int btotal = s[SCAN_BS - 1];

    if (tid == 0) {
        int prefix = 0;
        if (blk == 0) {
            atomicExch(&look[0], (u32)btotal | (2u << 24));
        } else {
            atomicExch(&look[blk], (u32)btotal | (1u << 24));
            int idx = blk - 1;
            while (true) {
                u32 w = atomicAdd(&look[idx], 0u);
                u32 st = w >> 24;
                if (st == 0) continue;
                prefix += (int)(w & 0xFFFFFFu);
                if (st == 2u) break;
                idx--;
            }
            atomicExch(&look[blk], (u32)(prefix + btotal) | (2u << 24));
        }
        sprefix = prefix;
    }
    __syncthreads();
    int run = sprefix + s[tid] - sum;
#pragma unroll
    for (int t = 0; t < SCAN_VT; t++) {
        int i = base + t;
        if (i < NN) {
            offs[i] = run;
            int c = v[t];
            inv[i] = c > 0 ? 1.0f / (float)c : 0.0f;
            run += c;
            cnt[i] = run;   // end-cursor = offs + degree
        }
    }
    if (blk == 0 && tid == 0) offs[NN] = NE;
}

__device__ __forceinline__ void decode(const void* hei, bool i32, int i, int& n, int& e) {
    if (i32) {
        n = ((const int*)hei)[i];
        e = ((const int*)hei)[NE + i];
    } else {
        n = (int)((const long long*)hei)[i];
        e = (int)((const long long*)hei)[NE + i];
    }
    n = clampi(n);
    e = clampi(e);
}

// ---- CSR fill per side: single atomicSub on end-cursor gives position ----
__global__ void k_fill_e(const void* __restrict__ hei) {
    int i = blockIdx.x * blockDim.x + threadIdx.x;
    if (i >= NE) return;
    bool i32 = (g_is_i32 != 0);
    int n, e;
    decode(hei, i32, i, n, e);
    int pe = atomicSub(&g_cnt_e[e], 1) - 1;
    g_csr_e[pe] = n;
}

__global__ void k_fill_n(const void* __restrict__ hei) {
    int i = blockIdx.x * blockDim.x + threadIdx.x;
    if (i >= NE) return;
    bool i32 = (g_is_i32 != 0);
    int n, e;
    decode(hei, i32, i, n, e);
    int pn = atomicSub(&g_cnt_n[n], 1) - 1;
    g_csr_n[pn] = e;
}

// ---- fp32 -> fp16 convert ----
__global__ void k_f2h(const float* __restrict__ src, __half* __restrict__ dst, int n4) {
    int i = blockIdx.x * blockDim.x + threadIdx.x;
    if (i < n4) {
        float4 v = ((const float4*)src)[i];
        __half2 h0 = __floats2half2_rn(v.x, v.y);
        __half2 h1 = __floats2half2_rn(v.z, v.w);
        uint2 o;
        o.x = *(u32*)&h0;
        o.y = *(u32*)&h1;
        ((uint2*)dst)[i] = o;
    }
}

// ---- tensor-core GEMM ----
__global__ __launch_bounds__(256) void k_gemm_mma(const __half* __restrict__ A,
                                                  const __half* __restrict__ Wh,
                                                  __half* __restrict__ C, int M) {
    extern __shared__ __half smem[];
    __half* sA = smem;
    __half* sB = smem + 128 * ASTRIDE;
    int tid = threadIdx.x;
    int rb = blockIdx.x * 128;

#pragma unroll
    for (int it = 0; it < 8; it++) {
        int idx = (it * 256 + tid) * 8;
        int r = idx >> 7, c = idx & 127;
        uint4 v = make_uint4(0, 0, 0, 0);
        if (rb + r < M) v = *(const uint4*)(A + (size_t)(rb + r) * HID + c);
        *(uint4*)(sA + r * ASTRIDE + c) = v;
    }
#pragma unroll
    for (int it = 0; it < 8; it++) {
        int idx = (it * 256 + tid) * 8;
        int r = idx >> 7, c = idx & 127;
        *(uint4*)(sB + r * ASTRIDE + c) = *(const uint4*)(Wh + r * HID + c);
    }
    __syncthreads();

    int w = tid >> 5, lane = tid & 31;
    int wm = (w & 3) * 32;
    int wn = (w >> 2) * 64;
    int lrow = (lane & 7) + ((lane >> 3) & 1) * 8;
    int lcol8 = (lane >> 4) * 8;

    float acc[2][8][4];
#pragma unroll
    for (int mi = 0; mi < 2; mi++)
#pragma unroll
        for (int nj = 0; nj < 8; nj++)
#pragma unroll
            for (int q = 0; q < 4; q++) acc[mi][nj][q] = 0.f;

#pragma unroll
    for (int ks = 0; ks < 8; ks++) {
        int k0 = ks * 16;
        u32 a[2][4];
#pragma unroll
        for (int mi = 0; mi < 2; mi++) {
            u32 ad = sptr(sA + (wm + mi * 16 + lrow) * ASTRIDE + k0 + lcol8);
            ldsm4(a[mi][0], a[mi][1], a[mi][2], a[mi][3], ad);
        }
        u32 b[8][2];
#pragma unroll
        for (int nj = 0; nj < 4; nj++) {
            u32 ad = sptr(sB + (k0 + lrow) * ASTRIDE + wn + nj * 16 + lcol8);
            u32 r0, r1, r2, r3;
            ldsm4t(r0, r1, r2, r3, ad);
            b[nj * 2][0] = r0; b[nj * 2][1] = r1;
            b[nj * 2 + 1][0] = r2; b[nj * 2 + 1][1] = r3;
        }
#pragma unroll
        for (int mi = 0; mi < 2; mi++)
#pragma unroll
            for (int nj = 0; nj < 8; nj++)
                mma16816(acc[mi][nj], a[mi], b[nj]);
    }

    int g = lane >> 2, t4 = lane & 3;
#pragma unroll
    for (int mi = 0; mi < 2; mi++) {
        int r0 = rb + wm + mi * 16 + g;
        int r1 = r0 + 8;
#pragma unroll
        for (int nj = 0; nj < 8; nj++) {
            int col = wn + nj * 8 + t4 * 2;
            if (r0 < M) {
                __half2 h = __floats2half2_rn(acc[mi][nj][0], acc[mi][nj][1]);
                *(__half2*)(C + (size_t)r0 * HID + col) = h;
            }
            if (r1 < M) {
                __half2 h = __floats2half2_rn(acc[mi][nj][2], acc[mi][nj][3]);
                *(__half2*)(C + (size_t)r1 * HID + col) = h;
            }
        }
    }
}

// ---- accumulate helper ----
__device__ __forceinline__ void acc_row(float4& acc, uint2 u) {
    float2 a0 = __half22float2(*(const __half2*)&u.x);
    float2 a1 = __half22float2(*(const __half2*)&u.y);
    acc.x += a0.x; acc.y += a0.y; acc.z += a1.x; acc.w += a1.y;
}

// ---- edge gather: m[e] = binv[e] * sum xw[n], 4-way unrolled ----
__global__ __launch_bounds__(256) void k_gather_e(const __half* __restrict__ src,
                                                  __half* __restrict__ dst) {
    int g = blockIdx.x * blockDim.x + threadIdx.x;
    int e = g >> 5;
    int lane = g & 31;
    if (e >= NN) return;
    int beg = g_offs_e[e];
    int end = g_offs_e[e + 1];
    float4 acc = make_float4(0.f, 0.f, 0.f, 0.f);
    const uint2* s2 = (const uint2*)src;
    int j = beg;
    for (; j + 3 < end; j += 4) {
        int i0 = g_csr_e[j], i1 = g_csr_e[j + 1], i2 = g_csr_e[j + 2], i3 = g_csr_e[j + 3];
        uint2 u0 = s2[(size_t)i0 * 32 + lane];
        uint2 u1 = s2[(size_t)i1 * 32 + lane];
        uint2 u2 = s2[(size_t)i2 * 32 + lane];
        uint2 u3 = s2[(size_t)i3 * 32 + lane];
        acc_row(acc, u0); acc_row(acc, u1); acc_row(acc, u2); acc_row(acc, u3);
    }
    for (; j < end; j++) {
        uint2 u0 = s2[(size_t)g_csr_e[j] * 32 + lane];
        acc_row(acc, u0);
    }
    float s = g_binv[e];
    __half2 o0 = __floats2half2_rn(acc.x * s, acc.y * s);
    __half2 o1 = __floats2half2_rn(acc.z * s, acc.w * s);
    uint2 ov;
    ov.x = *(const u32*)&o0;
    ov.y = *(const u32*)&o1;
    ((uint2*)dst)[(size_t)e * 32 + lane] = ov;
}

// ---- node gather, 4-way unrolled ----
template <bool RES, typename OUT>
__global__ __launch_bounds__(256) void k_gather_n(const __half* __restrict__ src,
                                                  const float* __restrict__ bias,
                                                  const float* __restrict__ pa,
                                                  const float* __restrict__ xres,
                                                  OUT* __restrict__ dst) {
    int g = blockIdx.x * blockDim.x + threadIdx.x;
    int n = g >> 5;
    int lane = g & 31;
    if (n >= NN) return;
    int beg = g_offs_n[n];
    int end = g_offs_n[n + 1];
    float4 acc = make_float4(0.f, 0.f, 0.f, 0.f);
    const uint2* s2 = (const uint2*)src;
    int j = beg;
    for (; j + 3 < end; j += 4) {
        int i0 = g_csr_n[j], i1 = g_csr_n[j + 1], i2 = g_csr_n[j + 2], i3 = g_csr_n[j + 3];
        uint2 u0 = s2[(size_t)i0 * 32 + lane];
        uint2 u1 = s2[(size_t)i1 * 32 + lane];
        uint2 u2 = s2[(size_t)i2 * 32 + lane];
        uint2 u3 = s2[(size_t)i3 * 32 + lane];
        acc_row(acc, u0); acc_row(acc, u1); acc_row(acc, u2); acc_row(acc, u3);
    }
    for (; j < end; j++) {
        uint2 u0 = s2[(size_t)g_csr_n[j] * 32 + lane];
        acc_row(acc, u0);
    }
    float d = g_dinv[n];
    float a = pa[0];
    float4 b = ((const float4*)bias)[lane];
    acc.x = acc.x * d + b.x;
    acc.y = acc.y * d + b.y;
    acc.z = acc.z * d + b.z;
    acc.w = acc.w * d + b.w;
    if (RES) {
        float4 xv = ((const float4*)xres)[(size_t)n * 32 + lane];
        acc.x += xv.x; acc.y += xv.y; acc.z += xv.z; acc.w += xv.w;
    }
    acc.x = acc.x >= 0.f ? acc.x : a * acc.x;
    acc.y = acc.y >= 0.f ? acc.y : a * acc.y;
    acc.z = acc.z >= 0.f ? acc.z : a * acc.z;
    acc.w = acc.w >= 0.f ? acc.w : a * acc.w;
    if (sizeof(OUT) == 2) {
        __half2 o0 = __floats2half2_rn(acc.x, acc.y);
        __half2 o1 = __floats2half2_rn(acc.z, acc.w);
        uint2 ov;
        ov.x = *(const u32*)&o0;
        ov.y = *(const u32*)&o1;
        ((uint2*)dst)[(size_t)n * 32 + lane] = ov;
    } else {
        ((float4*)dst)[(size_t)n * 32 + lane] = acc;
    }
}

extern "C" void kernel_launch(void* const* d_in, const int* in_sizes, int n_in,
                              void* d_out, int out_size) {
    (void)in_sizes; (void)n_in; (void)out_size;
    const float* x   = (const float*)d_in[0];
    const void*  hei = d_in[1];
    const float* W1  = (const float*)d_in[2];
    const float* b1  = (const float*)d_in[3];
    const float* W2  = (const float*)d_in[4];
    const float* b2  = (const float*)d_in[5];
    const float* pa  = (const float*)d_in[6];
    float* out = (float*)d_out;

    __half *pxh, *pw1h, *pw2h, *pxw, *pm, *ph;
    int *pcn, *pce, *pon, *poe;
    u32 *pln, *ple;
    float *pdi, *pbi;
    cudaGetSymbolAddress((void**)&pxh,  g_xh);
    cudaGetSymbolAddress((void**)&pw1h, g_w1h);
    cudaGetSymbolAddress((void**)&pw2h, g_w2h);
    cudaGetSymbolAddress((void**)&pxw,  g_xw);
    cudaGetSymbolAddress((void**)&pm,   g_m);
    cudaGetSymbolAddress((void**)&ph,   g_h);
    cudaGetSymbolAddress((void**)&pcn,  g_cnt_n);
    cudaGetSymbolAddress((void**)&pce,  g_cnt_e);
    cudaGetSymbolAddress((void**)&pon,  g_offs_n);
    cudaGetSymbolAddress((void**)&poe,  g_offs_e);
    cudaGetSymbolAddress((void**)&pln,  g_look_n);
    cudaGetSymbolAddress((void**)&ple,  g_look_e);
    cudaGetSymbolAddress((void**)&pdi,  g_dinv);
    cudaGetSymbolAddress((void**)&pbi,  g_binv);

    const int GW_BLOCKS = (NN * 32) / 256;
    const int GEMM_SMEM = 2 * 128 * ASTRIDE * 2;
    cudaFuncSetAttribute(k_gemm_mma, cudaFuncAttributeMaxDynamicSharedMemorySize, GEMM_SMEM);

    // fork
    cudaEventRecord(g_ss.evStart, 0);
    cudaStreamWaitEvent(g_ss.s1, g_ss.evStart, 0);
    cudaStreamWaitEvent(g_ss.s2, g_ss.evStart, 0);

    // stream 0: EDGE-side chain (critical for gather_e1)
    k_zero_e_detect<<<(NN + 255) / 256, 256>>>((const long long*)hei);
    cudaEventRecord(g_ss.evDetect, 0);
    k_deg_side<<<(NE / 2 + 255) / 256, 256>>>(hei, 1, pce);
    k_scan_s<<<SCAN_NBLK, SCAN_BS>>>(pce, poe, ple, pbi);
    k_fill_e<<<(NE + 255) / 256, 256>>>(hei);

    // s2: NODE-side chain
    k_zero_n<<<(NN + 255) / 256, 256, 0, g_ss.s2>>>();
    cudaStreamWaitEvent(g_ss.s2, g_ss.evDetect, 0);
    k_deg_side<<<(NE / 2 + 255) / 256, 256, 0, g_ss.s2>>>(hei, 0, pcn);
    k_scan_s<<<SCAN_NBLK, SCAN_BS, 0, g_ss.s2>>>(pcn, pon, pln, pdi);
    k_fill_n<<<(NE + 255) / 256, 256, 0, g_ss.s2>>>(hei);
    cudaEventRecord(g_ss.evFillN, g_ss.s2);

    // s1: fp16 conversions + GEMM1
    k_f2h<<<(NN * HID / 4 + 255) / 256, 256, 0, g_ss.s1>>>(x, pxh, NN * HID / 4);
    k_f2h<<<(HID * HID / 4 + 255) / 256, 256, 0, g_ss.s1>>>(W1, pw1h, HID * HID / 4);
    k_f2h<<<(HID * HID / 4 + 255) / 256, 256, 0, g_ss.s1>>>(W2, pw2h, HID * HID / 4);
    k_gemm_mma<<<(NN + 127) / 128, 256, GEMM_SMEM, g_ss.s1>>>(pxh, pw1h, pxw, NN);
    cudaEventRecord(g_ss.evGemm, g_ss.s1);

    // layer 1 aggregation
    cudaStreamWaitEvent(0, g_ss.evGemm, 0);
    k_gather_e<<<GW_BLOCKS, 256>>>(pxw, pm);
    cudaStreamWaitEvent(0, g_ss.evFillN, 0);
    k_gather_n<false, __half><<<GW_BLOCKS, 256>>>(pm, b1, pa, nullptr, ph);

    // layer 2
    k_gemm_mma<<<(NN + 127) / 128, 256, GEMM_SMEM>>>(ph, pw2h, pxw, NN);
    k_gather_e<<<GW_BLOCKS, 256>>>(pxw, pm);
    k_gather_n<true, float><<<GW_BLOCKS, 256>>>(pm, b2, pa, x, out);
}